// round 7
// baseline (speedup 1.0000x reference)
#include <cuda_runtime.h>

// CTC forward loss, T=512, N=32, C=8000, S=40 (Se = 2S+1 = 81).
//
// Radix-2 fused recurrence: two timesteps composed into one 5-term LSE.
//   alpha''[s] = l2[s] + LSE5(c0+A[s], c1+A[s-1], c2+A[s-2], c3+A[s-3], c4+A[s-4])
// with coefficients depending only on lp gathers and static skip gates:
//   c0 = l1[s]
//   c1 = lse2(l1[s], l1[s-1])
//   c2 = lse3(gs?l1[s], l1[s-1], gs?l1[s-2])
//   c3 = lse2(gsm1?l1[s-1], gs?l1[s-2])
//   c4 = (gs && gsm2) ? l1[s-2] : -inf
// The c's are independent of alpha -> computed in the stall shadows of the
// serial chain. Critical path per fused step (2 timesteps) ~= one LSE5.
//
// One block (128 threads, 4 warps) per batch element, ONE state per thread.
// Warp w covers states [18w, 18w+31] (14-lane overlap). In-warp neighbors via
// shfl.up (no barrier). Corruption from a warp's low edge spreads 4 lanes per
// fused step; refresh lanes 0..13 from warp w-1 (always-exact lanes 18..31)
// every K=3 fused steps -> one __syncthreads per 6 timesteps.
//
// Log2 domain throughout (LOG_TINY = ln(2^-126) -> exactly -126.0).

#define TT 512
#define NB 32
#define CC 8000
#define SS 40
#define SE 81
#define STRD 18
#define NFUSED 255    // fused steps cover t=1..510; final single step t=511
#define PF 6          // prefetch ring depth in fused steps

#define NEGF     (-1.0e30f)
#define INV_LN2  1.44269504088896341f
#define LN2      0.69314718055994531f

__device__ __forceinline__ float ex2f_(float x) {
    float y; asm("ex2.approx.ftz.f32 %0, %1;" : "=f"(y) : "f"(x)); return y;
}
__device__ __forceinline__ float lg2f_(float x) {
    float y; asm("lg2.approx.ftz.f32 %0, %1;" : "=f"(y) : "f"(x)); return y;
}

__device__ __forceinline__ float lse2_(float x, float y) {
    const float hi = fmaxf(x, y), lo = fminf(x, y);
    return hi + lg2f_(1.0f + ex2f_(lo - hi));
}

__global__ __launch_bounds__(128, 1)
void ctc_fused_kernel(const float* __restrict__ lp,      // (T, N, C)
                      const int*   __restrict__ targets, // (N, S)
                      const int*   __restrict__ tgt_len, // (N,)
                      float*       __restrict__ out)     // (N,)
{
    const int n   = blockIdx.x;
    const int tid = threadIdx.x;
    const int w   = tid >> 5;
    const int L   = tid & 31;

    const int s_nom = STRD * w + L;                  // may exceed 80 (warp 3)
    const int s     = (s_nom <= SE - 1) ? s_nom : (SE - 1);

    // Static structure: class of state s, and skip gates at s, s-1, s-2.
    // skip(x): x odd, x>=3, targets[(x-1)/2] != targets[(x-3)/2].
    const int* tg = targets + n * SS;
    int cls = (s & 1) ? tg[s >> 1] : 0;
    auto skipf = [&](int x) -> bool {
        return (x >= 3) && (x & 1) && (tg[x >> 1] != tg[(x - 3) >> 1]);
    };
    const bool gs   = skipf(s);
    const bool gsm1 = skipf(s - 1);
    const bool gsm2 = skipf(s - 2);

    // Warp-0 boundary masks for shfl.up results (other warps' low lanes are
    // in the corruption-tolerated overlap region; leave them stale-finite).
    const bool w0 = (w == 0);
    const bool b1 = !(w0 && L < 1);
    const bool b2 = !(w0 && L < 2);
    const bool b3 = !(w0 && L < 3);
    const bool b4 = !(w0 && L < 4);

    const unsigned base   = (unsigned)n * CC + (unsigned)cls;
    const unsigned stride = (unsigned)NB * CC;

    __shared__ float xfer[2][4][14];
    __shared__ float fin[SE];

    // t = 0 init (log2 domain).
    float a;
    {
        const float l0 = __ldg(lp + base) * INV_LN2;
        a = (s_nom <= 1) ? l0 : -126.0f;
    }

    // Final-step lp (t = 511), loaded once.
    const float lfin = __ldg(lp + base + (unsigned)(TT - 1) * stride) * INV_LN2;

    // Prefetch ring: fused step i uses t1 = 1+2i, t2 = 2+2i.
    float ring1[PF], ring2[PF];
#pragma unroll
    for (int j = 0; j < PF; ++j) {
        const unsigned o1 = (unsigned)(1 + 2 * j) * stride;
        ring1[j] = __ldg(lp + base + o1);
        ring2[j] = __ldg(lp + base + o1 + stride);
    }

    int par = 0;
#pragma unroll 1
    for (int ib = 0; ib < NFUSED; ib += PF) {
#pragma unroll
        for (int j = 0; j < PF; ++j) {
            const int i = ib + j;
            if (i < NFUSED) {
                const float l1 = ring1[j] * INV_LN2;
                const float l2 = ring2[j] * INV_LN2;
                if (i + PF < NFUSED) {
                    const unsigned o1 = (unsigned)(1 + 2 * (i + PF)) * stride;
                    ring1[j] = __ldg(lp + base + o1);
                    ring2[j] = __ldg(lp + base + o1 + stride);
                }

                // ---- coefficients (independent of alpha; fill stall slots)
                const float l1m1 = __shfl_up_sync(0xffffffffu, l1, 1);
                const float l1m2 = __shfl_up_sync(0xffffffffu, l1, 2);
                const float c1 = lse2_(l1, l1m1);
                float c2;
                {
                    const float x = gs ? l1 : NEGF;
                    const float z = gs ? l1m2 : NEGF;
                    const float hi = fmaxf(x, l1m1), lo = fminf(x, l1m1);
                    const float m  = fmaxf(hi, z),   zz = fminf(hi, z);
                    c2 = m + lg2f_(1.0f + ex2f_(lo - m) + ex2f_(zz - m));
                }
                const float c3 = lse2_(gsm1 ? l1m1 : NEGF, gs ? l1m2 : NEGF);
                const float c4 = (gs && gsm2) ? l1m2 : NEGF;

                // ---- critical chain
                float p1 = __shfl_up_sync(0xffffffffu, a, 1);
                float p2 = __shfl_up_sync(0xffffffffu, a, 2);
                float p3 = __shfl_up_sync(0xffffffffu, a, 3);
                float p4 = __shfl_up_sync(0xffffffffu, a, 4);
                p1 = b1 ? p1 : NEGF;
                p2 = b2 ? p2 : NEGF;
                p3 = b3 ? p3 : NEGF;
                p4 = b4 ? p4 : NEGF;

                const float v0 = a  + l1;    // c0 = l1[s]
                const float v1 = c1 + p1;
                const float v2 = c2 + p2;
                const float v3 = c3 + p3;
                const float v4 = c4 + p4;

                const float m = fmaxf(fmaxf(fmaxf(v0, v1), fmaxf(v2, v3)), v4);
                const float sum = ex2f_(v0 - m) + ex2f_(v1 - m) + ex2f_(v2 - m)
                                + ex2f_(v3 - m) + ex2f_(v4 - m);
                a = m + lg2f_(sum) + l2;

                // ---- refresh every 3 fused steps (corruption <= 12 lanes)
                if ((j % 3) == 2) {
                    if (L >= STRD) xfer[par][w][L - STRD] = a;
                    __syncthreads();
                    if (w > 0 && L < 14) a = xfer[par][w - 1][L];
                    par ^= 1;
                }
            }
        }
    }
    // NFUSED = 255 = 3*85: the last fused step (i=254, j%3==2) was followed by
    // a refresh, so all lanes' values entering the final step are exact where
    // needed.

    // Final single step, t = 511.
    {
        float p1 = __shfl_up_sync(0xffffffffu, a, 1);
        float p2 = __shfl_up_sync(0xffffffffu, a, 2);
        p1 = b1 ? p1 : NEGF;
        p2 = b2 ? p2 : NEGF;
        const float p2v = gs ? p2 : NEGF;
        const float hi = fmaxf(a, p1), lo = fminf(a, p1);
        const float m  = fmaxf(hi, p2v), z = fminf(hi, p2v);
        a = m + lg2f_(1.0f + ex2f_(lo - m) + ex2f_(z - m)) + lfin;
    }

    // Owned (always-exact) lanes publish final alphas.
    const bool owner = (w == 0) || (L >= 14 && s_nom <= SE - 1);
    if (owner) fin[s_nom] = a;
    __syncthreads();

    if (tid == 0) {
        const int   Ln   = tgt_len[n];
        const int   len  = 2 * Ln + 1;
        const float al   = fin[len - 1];
        const float ap   = fin[len - 2];
        const float x    = fmaxf(al, ap);
        const float y    = fminf(al, ap);
        const float loss = (x + lg2f_(1.0f + ex2f_(y - x))) * LN2;  // back to ln
        out[n] = -loss / (float)Ln;
    }
}

extern "C" void kernel_launch(void* const* d_in, const int* in_sizes, int n_in,
                              void* d_out, int out_size) {
    const float* lp      = (const float*)d_in[0];  // log_probs (T, N, C)
    const int*   targets = (const int*)  d_in[1];  // (N, S)
    // d_in[2] = input_lengths — reference ignores them (always full T)
    const int*   tlen    = (const int*)  d_in[3];  // (N,)
    ctc_fused_kernel<<<NB, 128>>>(lp, targets, tlen, (float*)d_out);
}

// round 12
// speedup vs baseline: 2.3125x; 2.3125x over previous
#include <cuda_runtime.h>
#include <math.h>

// CTC forward loss, T=512, N=32, C=8000, S=40 (Se = 2S+1 = 81).
//
// LINEAR-domain scaled forward algorithm. One warp per batch element,
// 3 consecutive states per lane (lanes 0-26 real; lanes 27-31 DEAD).
//   a'[s] = (a[s] + a[s-1] + skip(s)*a[s-2]) * p[t, class(s)]
// is FADD+FFMA+FMUL per state — no transcendentals on the recurrence chain.
//
// Numerics:
//  * p = ex2(lp*INV_LN2 + boost_k): boost_k = +13 for LIVE states
//    (s <= 2*target_len, lane <= 26) and -1e30 for DEAD states, so dead
//    states hold exactly 0 forever. Flow is s-increasing, so zeroed dead
//    states never corrupt live ones. This keeps the warp-max renorm keyed
//    to the live top states (= the ones read at the end), preventing the
//    FTZ flush-to-zero failure of the previous round.
//  * Every 8 steps, renormalize all alphas by an EXACT power of two derived
//    from the warp-max exponent field; the butterfly max-reduce is spread
//    one stage per step so its latency hides in the chain's stall slots.
//    The integer exponent is accumulated and undone at the end — bit-exact.
//
// Final loss: log2 via frexpf + one lg2, converted back to ln.

#define TT 512
#define NB 32
#define CC 8000
#define SS 40
#define SE 81
#define PF 8
#define STRIDE (NB * CC)

#define BOOST    13.0f
#define NEGBIG   (-1.0e30f)
#define INV_LN2  1.44269504088896341f
#define LN2      0.69314718055994531f

__device__ __forceinline__ float ex2f_(float x) {
    float y; asm("ex2.approx.ftz.f32 %0, %1;" : "=f"(y) : "f"(x)); return y;
}
__device__ __forceinline__ float lg2f_(float x) {
    float y; asm("lg2.approx.ftz.f32 %0, %1;" : "=f"(y) : "f"(x)); return y;
}

// One timestep: exponentiate ring slot (off-chain), reload ring, shuffle
// neighbors, linear recurrence. jslot is a compile-time ring index.
// bst0/1/2 carry the validity gate (dead state -> arg ~ -1e30 -> p = 0).
#define STEP(jslot, t_) do {                                                   \
    const float l0 = ex2f_(__fmaf_rn(r0[jslot], INV_LN2, bst0));               \
    const float l1 = ex2f_(__fmaf_rn(r1[jslot], INV_LN2, bst1));               \
    const float l2 = ex2f_(__fmaf_rn(r2[jslot], INV_LN2, bst2));               \
    if ((t_) + PF < TT) {                                                      \
        const unsigned off = (unsigned)((t_) + PF) * (unsigned)STRIDE;         \
        r0[jslot] = __ldg(q0 + off);                                           \
        r1[jslot] = __ldg(q1 + off);                                           \
        r2[jslot] = __ldg(q2 + off);                                           \
    }                                                                          \
    float p1v = __shfl_up_sync(0xffffffffu, a1, 1);                            \
    float p2v = __shfl_up_sync(0xffffffffu, a2, 1);                            \
    p1v = (lane == 0) ? 0.0f : p1v;                                            \
    p2v = (lane == 0) ? 0.0f : p2v;                                            \
    const float n0 = __fmaf_rn(sk0, p1v, a0 + p2v) * l0;                       \
    const float n1 = __fmaf_rn(sk1, p2v, a1 + a0)  * l1;                       \
    const float n2 = __fmaf_rn(sk2, a0,  a2 + a1)  * l2;                       \
    a0 = n0; a1 = n1; a2 = n2;                                                 \
} while (0)

__global__ __launch_bounds__(32, 1)
void ctc_lin_kernel(const float* __restrict__ lp,      // (T, N, C)
                    const int*   __restrict__ targets, // (N, S)
                    const int*   __restrict__ tgt_len, // (N,)
                    float*       __restrict__ out)     // (N,)
{
    const int n    = blockIdx.x;
    const int lane = threadIdx.x;
    // Lane owns states sb, sb+1, sb+2. Lanes 27-31 are dead (all-zero).
    const int sb   = (lane <= 26) ? 3 * lane : (SE - 3);
    const int Ln   = tgt_len[n];
    const int smax = 2 * Ln;               // highest live state (= len-1)

    const int* tg = targets + n * SS;
    int   cls[3];
    float skf[3];
    float bst[3];
#pragma unroll
    for (int k = 0; k < 3; ++k) {
        const int s = sb + k;
        if (s & 1) {
            cls[k] = tg[s >> 1];
            skf[k] = (s >= 3 && cls[k] != tg[(s - 3) >> 1]) ? 1.0f : 0.0f;
        } else {
            cls[k] = 0;           // blank; blanks never skip
            skf[k] = 0.0f;
        }
        bst[k] = (lane <= 26 && s <= smax) ? BOOST : NEGBIG;  // dead -> p = 0
    }
    const float sk0 = skf[0], sk1 = skf[1], sk2 = skf[2];
    const float bst0 = bst[0], bst1 = bst[1], bst2 = bst[2];

    const float* q0 = lp + (unsigned)n * CC + (unsigned)cls[0];
    const float* q1 = lp + (unsigned)n * CC + (unsigned)cls[1];
    const float* q2 = lp + (unsigned)n * CC + (unsigned)cls[2];

    // t = 0 init (boosted linear domain). States 0 and 1 are always live
    // (len >= 21). LOG_TINY elsewhere -> ~2^-168 boosted -> 0.
    float a0 = 0.0f, a1 = 0.0f, a2 = 0.0f;
    if (sb == 0) {
        a0 = ex2f_(__fmaf_rn(__ldg(q0), INV_LN2, BOOST));
        a1 = ex2f_(__fmaf_rn(__ldg(q1), INV_LN2, BOOST));
    }

    // Prefetch ring for t = 1..PF.
    float r0[PF], r1[PF], r2[PF];
#pragma unroll
    for (int j = 0; j < PF; ++j) {
        const unsigned off = (unsigned)(j + 1) * (unsigned)STRIDE;
        r0[j] = __ldg(q0 + off);
        r1[j] = __ldg(q1 + off);
        r2[j] = __ldg(q2 + off);
    }

    int lcr = 0;   // accumulated renorm log2 (warp-uniform)

    // 63 blocks of 8 steps: t = 1..504. Renorm butterfly spread across the
    // block: sample after j=0, one reduce stage per step, apply after j=7.
#pragma unroll 1
    for (int tb = 1; tb <= 497; tb += 8) {
        float m;
        STEP(0, tb + 0); m = fmaxf(fmaxf(a0, a1), a2);
        STEP(1, tb + 1); m = fmaxf(m, __shfl_xor_sync(0xffffffffu, m, 1));
        STEP(2, tb + 2); m = fmaxf(m, __shfl_xor_sync(0xffffffffu, m, 2));
        STEP(3, tb + 3); m = fmaxf(m, __shfl_xor_sync(0xffffffffu, m, 4));
        STEP(4, tb + 4); m = fmaxf(m, __shfl_xor_sync(0xffffffffu, m, 8));
        STEP(5, tb + 5); m = fmaxf(m, __shfl_xor_sync(0xffffffffu, m, 16));
        int g; float sc;
        STEP(6, tb + 6);
        {
            const int E = (__float_as_int(m) >> 23) & 255;  // m > 0 (live states)
            g  = 127 - E;                                   // scale = 2^g (exact)
            sc = __int_as_float((127 + g) << 23);
        }
        STEP(7, tb + 7);
        a0 *= sc; a1 *= sc; a2 *= sc;
        lcr += g;
    }

    // Remainder: t = 505..511 (ring already holds them; drift over 7 steps
    // since the last renorm is a few bits — safe).
    STEP(0, 505); STEP(1, 506); STEP(2, 507); STEP(3, 508);
    STEP(4, 509); STEP(5, 510); STEP(6, 511);

    // Publish final alphas from owner lanes (0..26).
    __shared__ float fin[SE];
    if (lane <= 26) { fin[sb] = a0; fin[sb + 1] = a1; fin[sb + 2] = a2; }
    __syncwarp();

    if (lane == 0) {
        const int   len  = 2 * Ln + 1;
        const float ssum = fin[len - 1] + fin[len - 2];   // top live states ~O(1)
        int e2; const float mant = frexpf(ssum, &e2);
        const float log2a = lg2f_(mant) + (float)e2;
        // Undo renorms and the 512 per-step boosts (t=0 init + 511 steps).
        const float logP_ln = (log2a - (float)lcr - BOOST * 512.0f) * LN2;
        out[n] = -logP_ln / (float)Ln;
    }
}

extern "C" void kernel_launch(void* const* d_in, const int* in_sizes, int n_in,
                              void* d_out, int out_size) {
    const float* lp      = (const float*)d_in[0];  // log_probs (T, N, C)
    const int*   targets = (const int*)  d_in[1];  // (N, S)
    // d_in[2] = input_lengths — reference ignores them (always full T)
    const int*   tlen    = (const int*)  d_in[3];  // (N,)
    ctc_lin_kernel<<<NB, 32>>>(lp, targets, tlen, (float*)d_out);
}